// round 15
// baseline (speedup 1.0000x reference)
#include <cuda_runtime.h>
#include <cuda_fp16.h>

// V=100000, K=32, F=64.
// out[v, 0:64]   = mean over K neighbours of x[idxs[v,k], :]
// out[v, 64:128] = max  over K neighbours
//
// Two kernels + PDL. Gather body = R14 (2 vertices/warp, half-warp per row,
// paired asm loads -> 2 lines/request, HADD2/HMAX2, .cs stores).
// R15 change: GRID-STRIDE persistent-ish gather -- exactly one CTA wave
// (148 SMs x 7 CTAs) instead of 12500 short-lived CTAs (~320ns each, 84
// waves). Removes CTA launch/drain churn + cross-wave L1tex-queue spread,
// which is the remaining candidate for the 46% issue duty-cycle cap.
// No fusion, no grid barrier (R8's confounds).

#define KNN  32
#define FDIM 64
#define VMAX 100000
#define GATHER_CTAS (148 * 7)

__device__ __align__(16) __half2 g_xh[VMAX * (FDIM / 2)];   // 12.8 MB

__global__ __launch_bounds__(256)
void convert_kernel(const float4* __restrict__ x4, int n8)   // n8 = V*F/8
{
    int i = blockIdx.x * blockDim.x + threadIdx.x;
    if (i < n8) {
        float4 a = x4[2 * i];
        float4 b = x4[2 * i + 1];
        __half2 h0 = __floats2half2_rn(a.x, a.y);
        __half2 h1 = __floats2half2_rn(a.z, a.w);
        __half2 h2 = __floats2half2_rn(b.x, b.y);
        __half2 h3 = __floats2half2_rn(b.z, b.w);
        int4 packed;
        packed.x = *(const int*)&h0;
        packed.y = *(const int*)&h1;
        packed.z = *(const int*)&h2;
        packed.w = *(const int*)&h3;
        *reinterpret_cast<int4*>(&g_xh[4 * i]) = packed;
    }
    asm volatile("griddepcontrol.launch_dependents;" ::: "memory");
}

__device__ __forceinline__ void stg_cs_f4(float4* p, float4 v)
{
    asm volatile("st.global.cs.v4.f32 [%0], {%1,%2,%3,%4};"
                 :: "l"(p), "f"(v.x), "f"(v.y), "f"(v.z), "f"(v.w)
                 : "memory");
}

__global__ __launch_bounds__(256, 7)   // 36-reg budget
void knn_mean_max_kernel(const int2* __restrict__ idx2,
                         float4*     __restrict__ out4,
                         int V)
{
    const int lane = threadIdx.x & 31;
    const int h    = lane >> 4;        // which vertex of the pair
    const int hl   = lane & 15;        // position within half-warp
    const int warp0   = (blockIdx.x * blockDim.x + threadIdx.x) >> 5;
    const int wstride = (GATHER_CTAS * 256) >> 5;   // total warps
    const int npairs  = (V + 1) / 2;

    // Block until convert's g_xh writes are visible (before any g_xh read).
    asm volatile("griddepcontrol.wait;" ::: "memory");

    const __half2 zero = __float2half2_rn(0.0f);
    const __half2 ninf = __float2half2_rn(-65504.0f);
    const int srcbase = lane & 16;     // shuffles stay within the half-warp
    const float inv = 1.0f / KNN;

    // Lane reads half2 pair (8B) at offset hl of each gathered row
    // (row = 32 half2 = 128B; 16 lanes * 8B cover it).
    const __half2* __restrict__ xl = g_xh + 2 * hl;

    for (int w = warp0; w < npairs; w += wstride) {
        const int v = 2 * w + h;       // this half-warp's vertex
        // Coalesced idx load: lanes 0..31 cover 256B = idxs of both
        // vertices of the pair. (v < V always holds except possibly the
        // single odd tail vertex; V=100000 is even, but guard anyway.)
        int2 pair = make_int2(0, 0);
        if (v < V) pair = idx2[v * (KNN / 2) + hl];

        __half2 sa0 = zero, sa1 = zero, sb0 = zero, sb1 = zero;
        __half2 m0 = ninf, m1 = ninf;

        #pragma unroll
        for (int kk = 0; kk < KNN / 2; ++kk) {
            // k = 2*kk and k+1 live in the SAME source lane's int2.
            const int src  = srcbase + kk;
            const int idxE = __shfl_sync(0xffffffffu, pair.x, src);
            const int idxO = __shfl_sync(0xffffffffu, pair.y, src);
            const __half2* pE = xl + (size_t)(unsigned)idxE * (FDIM / 2);
            const __half2* pO = xl + (size_t)(unsigned)idxO * (FDIM / 2);

            // Both loads in ONE asm block: MLP=2 guaranteed.
            unsigned int e0, e1, o0, o1;
            asm volatile(
                "ld.global.nc.v2.u32 {%0,%1}, [%4];\n\t"
                "ld.global.nc.v2.u32 {%2,%3}, [%5];\n\t"
                : "=r"(e0), "=r"(e1), "=r"(o0), "=r"(o1)
                : "l"(pE), "l"(pO));

            const __half2 ea = *(const __half2*)&e0;
            const __half2 eb = *(const __half2*)&e1;
            const __half2 oa = *(const __half2*)&o0;
            const __half2 ob = *(const __half2*)&o1;
            sa0 = __hadd2(sa0, ea);  sa1 = __hadd2(sa1, eb);
            sb0 = __hadd2(sb0, oa);  sb1 = __hadd2(sb1, ob);
            m0 = __hmax2(m0, ea);    m1 = __hmax2(m1, eb);
            m0 = __hmax2(m0, oa);    m1 = __hmax2(m1, ob);
        }

        if (v >= V) continue;

        const float2 f0a = __half22float2(sa0), f0b = __half22float2(sb0);
        const float2 f1a = __half22float2(sa1), f1b = __half22float2(sb1);
        const float2 fm0 = __half22float2(m0),  fm1 = __half22float2(m1);

        // Lane holds features [4*hl, 4*hl+4) of vertex v.
        // out row = 128 floats = 32 float4: [mean 16 | max 16] float4.
        float4 mean = make_float4((f0a.x + f0b.x) * inv,
                                  (f0a.y + f0b.y) * inv,
                                  (f1a.x + f1b.x) * inv,
                                  (f1a.y + f1b.y) * inv);
        float4 mx   = make_float4(fm0.x, fm0.y, fm1.x, fm1.y);

        stg_cs_f4(&out4[v * 32 + hl],      mean);
        stg_cs_f4(&out4[v * 32 + 16 + hl], mx);
    }
}

extern "C" void kernel_launch(void* const* d_in, const int* in_sizes, int n_in,
                              void* d_out, int out_size)
{
    const float4* x4   = (const float4*)d_in[0];  // x: [V, 64] float32
    const int2*   idx2 = (const int2*)d_in[1];    // idxs: [V, 32] int32
    float4*       out4 = (float4*)d_out;          // out: [V, 128] float32

    const int V  = in_sizes[0] / FDIM;            // 100000
    const int n8 = in_sizes[0] / 8;               // V*F/8 (16B per thread)

    convert_kernel<<<(n8 + 255) / 256, 256>>>(x4, n8);

    cudaLaunchConfig_t cfg = {};
    cfg.gridDim  = dim3(GATHER_CTAS, 1, 1);
    cfg.blockDim = dim3(256, 1, 1);
    cfg.dynamicSmemBytes = 0;
    cfg.stream = 0;

    cudaLaunchAttribute attrs[1];
    attrs[0].id = cudaLaunchAttributeProgrammaticStreamSerialization;
    attrs[0].val.programmaticStreamSerializationAllowed = 1;
    cfg.attrs = attrs;
    cfg.numAttrs = 1;

    cudaLaunchKernelEx(&cfg, knn_mean_max_kernel, idx2, out4, V);
}

// round 16
// speedup vs baseline: 1.2971x; 1.2971x over previous
#include <cuda_runtime.h>
#include <cuda_fp16.h>

// V=100000, K=32, F=64.
// out[v, 0:64]   = mean over K neighbours of x[idxs[v,k], :]
// out[v, 64:128] = max  over K neighbours
//
// Two kernels + PDL. R16 gather: 2 vertices/warp; within each half-warp,
// lanes hl<8 cover row k and lanes hl>=8 cover row k+1, each lane loading
// int4 (16B) -> ONE LDG.128 per warp-iteration gathers 4 rows (same 4
// cache lines as R14's two LDG.64s, with half the LDG/address instructions).
// Even-k / odd-k partials are combined once per vertex with shfl-xor-8.

#define KNN  32
#define FDIM 64
#define VMAX 100000

__device__ __align__(16) __half2 g_xh[VMAX * (FDIM / 2)];   // 12.8 MB

__global__ __launch_bounds__(256)
void convert_kernel(const float4* __restrict__ x4, int n8)   // n8 = V*F/8
{
    int i = blockIdx.x * blockDim.x + threadIdx.x;
    if (i < n8) {
        float4 a = x4[2 * i];
        float4 b = x4[2 * i + 1];
        __half2 h0 = __floats2half2_rn(a.x, a.y);
        __half2 h1 = __floats2half2_rn(a.z, a.w);
        __half2 h2 = __floats2half2_rn(b.x, b.y);
        __half2 h3 = __floats2half2_rn(b.z, b.w);
        int4 packed;
        packed.x = *(const int*)&h0;
        packed.y = *(const int*)&h1;
        packed.z = *(const int*)&h2;
        packed.w = *(const int*)&h3;
        *reinterpret_cast<int4*>(&g_xh[4 * i]) = packed;
    }
    asm volatile("griddepcontrol.launch_dependents;" ::: "memory");
}

__device__ __forceinline__ void stg_cs_f4(float4* p, float4 v)
{
    asm volatile("st.global.cs.v4.f32 [%0], {%1,%2,%3,%4};"
                 :: "l"(p), "f"(v.x), "f"(v.y), "f"(v.z), "f"(v.w)
                 : "memory");
}

__device__ __forceinline__ __half2 h2_shfl_xor8(__half2 v)
{
    unsigned int u = *(const unsigned int*)&v;
    u = __shfl_xor_sync(0xffffffffu, u, 8);
    return *(const __half2*)&u;
}

__global__ __launch_bounds__(256, 7)   // 36-reg budget
void knn_mean_max_kernel(const int2* __restrict__ idx2,
                         float4*     __restrict__ out4,
                         int V)
{
    const int warp = (blockIdx.x * blockDim.x + threadIdx.x) >> 5;
    const int lane = threadIdx.x & 31;
    const int h    = lane >> 4;        // which vertex of the pair
    const int hl   = lane & 15;        // position within half-warp
    const int r    = hl >> 3;          // 0: even-k rows, 1: odd-k rows
    const int p8   = hl & 7;           // 16B-chunk position within the row
    const int v    = 2 * warp + h;     // this half-warp's vertex
    const bool active = (v < V);

    // Coalesced idx load: lanes 0..31 cover 256B = idxs of both vertices.
    // Lane hl of half-warp h holds idxs[v][2*hl], idxs[v][2*hl+1].
    int2 pair = make_int2(0, 0);
    if (active) pair = idx2[v * (KNN / 2) + hl];

    // Block until convert's g_xh writes are visible.
    asm volatile("griddepcontrol.wait;" ::: "memory");

    if (!active) return;

    const __half2 zero = __float2half2_rn(0.0f);
    const __half2 ninf = __float2half2_rn(-65504.0f);
    __half2 s0 = zero, s1 = zero, s2 = zero, s3 = zero;  // this lane's k-half
    __half2 m0 = ninf, m1 = ninf, m2 = ninf, m3 = ninf;

    // Lane reads int4 chunk p8 (16B) of its row; 8 lanes cover the 128B row.
    const int4* __restrict__ xl = reinterpret_cast<const int4*>(g_xh) + p8;
    const int srcbase = lane & 16;     // shuffles stay within the half-warp

    #pragma unroll
    for (int kk = 0; kk < KNN / 2; ++kk) {
        // Source lane srcbase+kk holds (idx[2kk], idx[2kk+1]) of my vertex.
        const int src = srcbase + kk;
        const int iE  = __shfl_sync(0xffffffffu, pair.x, src);
        const int iO  = __shfl_sync(0xffffffffu, pair.y, src);
        const int idx = r ? iO : iE;   // my half covers even or odd k

        // One LDG.128 per warp-iter: 32 lanes x 16B = 4 rows (4 lines).
        const int4 d = __ldg(xl + (size_t)(unsigned)idx * 8);  // row = 8 int4
        const __half2 a0 = *(const __half2*)&d.x;
        const __half2 a1 = *(const __half2*)&d.y;
        const __half2 a2 = *(const __half2*)&d.z;
        const __half2 a3 = *(const __half2*)&d.w;
        s0 = __hadd2(s0, a0);  m0 = __hmax2(m0, a0);
        s1 = __hadd2(s1, a1);  m1 = __hmax2(m1, a1);
        s2 = __hadd2(s2, a2);  m2 = __hmax2(m2, a2);
        s3 = __hadd2(s3, a3);  m3 = __hmax2(m3, a3);
    }

    // Combine even-k and odd-k partials: lane hl and hl^8 hold the same
    // chunk p8 of the same vertex.
    const __half2 st0 = __hadd2(s0, h2_shfl_xor8(s0));
    const __half2 st1 = __hadd2(s1, h2_shfl_xor8(s1));
    const __half2 st2 = __hadd2(s2, h2_shfl_xor8(s2));
    const __half2 st3 = __hadd2(s3, h2_shfl_xor8(s3));
    const __half2 mt0 = __hmax2(m0, h2_shfl_xor8(m0));
    const __half2 mt1 = __hmax2(m1, h2_shfl_xor8(m1));
    const __half2 mt2 = __hmax2(m2, h2_shfl_xor8(m2));
    const __half2 mt3 = __hmax2(m3, h2_shfl_xor8(m3));

    // Lane's chunk p8 = features [8*p8, 8*p8+8) = 2 float4 of the output.
    // out row = 128 floats = 32 float4: [mean 16 float4 | max 16 float4].
    if (r == 0) {     // lanes hl<8 store the mean
        const float inv = 1.0f / KNN;
        const float2 f0 = __half22float2(st0), f1 = __half22float2(st1);
        const float2 f2 = __half22float2(st2), f3 = __half22float2(st3);
        float4 lo = make_float4(f0.x * inv, f0.y * inv, f1.x * inv, f1.y * inv);
        float4 hi = make_float4(f2.x * inv, f2.y * inv, f3.x * inv, f3.y * inv);
        stg_cs_f4(&out4[v * 32 + 2 * p8],     lo);
        stg_cs_f4(&out4[v * 32 + 2 * p8 + 1], hi);
    } else {          // lanes hl>=8 store the max
        const float2 f0 = __half22float2(mt0), f1 = __half22float2(mt1);
        const float2 f2 = __half22float2(mt2), f3 = __half22float2(mt3);
        float4 lo = make_float4(f0.x, f0.y, f1.x, f1.y);
        float4 hi = make_float4(f2.x, f2.y, f3.x, f3.y);
        stg_cs_f4(&out4[v * 32 + 16 + 2 * p8],     lo);
        stg_cs_f4(&out4[v * 32 + 16 + 2 * p8 + 1], hi);
    }
}

extern "C" void kernel_launch(void* const* d_in, const int* in_sizes, int n_in,
                              void* d_out, int out_size)
{
    const float4* x4   = (const float4*)d_in[0];  // x: [V, 64] float32
    const int2*   idx2 = (const int2*)d_in[1];    // idxs: [V, 32] int32
    float4*       out4 = (float4*)d_out;          // out: [V, 128] float32

    const int V  = in_sizes[0] / FDIM;            // 100000
    const int n8 = in_sizes[0] / 8;               // V*F/8 (16B per thread)

    convert_kernel<<<(n8 + 255) / 256, 256>>>(x4, n8);

    const int warps = (V + 1) / 2;                // 2 vertices per warp
    const int blocks = (warps + 7) / 8;           // 8 warps per block

    cudaLaunchConfig_t cfg = {};
    cfg.gridDim  = dim3((unsigned)blocks, 1, 1);
    cfg.blockDim = dim3(256, 1, 1);
    cfg.dynamicSmemBytes = 0;
    cfg.stream = 0;

    cudaLaunchAttribute attrs[1];
    attrs[0].id = cudaLaunchAttributeProgrammaticStreamSerialization;
    attrs[0].val.programmaticStreamSerializationAllowed = 1;
    cfg.attrs = attrs;
    cfg.numAttrs = 1;

    cudaLaunchKernelEx(&cfg, knn_mean_max_kernel, idx2, out4, V);
}

// round 17
// speedup vs baseline: 1.3769x; 1.0615x over previous
#include <cuda_runtime.h>
#include <cuda_fp16.h>

// V=100000, K=32, F=64.
// out[v, 0:64]   = mean over K neighbours of x[idxs[v,k], :]
// out[v, 64:128] = max  over K neighbours
//
// CONVERGED DESIGN (R14 + convert micro-vectorization):
//   convert: x fp32 -> fp16 scratch, 32B per thread; PDL launch_dependents.
//   gather:  2 vertices/warp, half-warp per row, paired asm LDG.64s
//            (2 cache lines per request = measured optimum), HADD2/HMAX2,
//            shuffle-free .cs epilogue.
// The gather sits at a coding-invariant HW floor (~27us): 3.2M line-misses
// per pass bounded by per-SM in-flight miss capacity x L2 latency. Convert
// (~3.5us) is at its DRAM-read floor; PDL hides most of the launch gap.

#define KNN  32
#define FDIM 64
#define VMAX 100000

__device__ __align__(16) __half2 g_xh[VMAX * (FDIM / 2)];   // 12.8 MB

__global__ __launch_bounds__(256)
void convert_kernel(const float4* __restrict__ x4, int n16)  // n16 = V*F/16
{
    int i = blockIdx.x * blockDim.x + threadIdx.x;
    if (i < n16) {
        float4 a = x4[4 * i];
        float4 b = x4[4 * i + 1];
        float4 c = x4[4 * i + 2];
        float4 e = x4[4 * i + 3];
        __half2 h0 = __floats2half2_rn(a.x, a.y);
        __half2 h1 = __floats2half2_rn(a.z, a.w);
        __half2 h2 = __floats2half2_rn(b.x, b.y);
        __half2 h3 = __floats2half2_rn(b.z, b.w);
        __half2 h4 = __floats2half2_rn(c.x, c.y);
        __half2 h5 = __floats2half2_rn(c.z, c.w);
        __half2 h6 = __floats2half2_rn(e.x, e.y);
        __half2 h7 = __floats2half2_rn(e.z, e.w);
        int4 p0, p1;
        p0.x = *(const int*)&h0;  p0.y = *(const int*)&h1;
        p0.z = *(const int*)&h2;  p0.w = *(const int*)&h3;
        p1.x = *(const int*)&h4;  p1.y = *(const int*)&h5;
        p1.z = *(const int*)&h6;  p1.w = *(const int*)&h7;
        reinterpret_cast<int4*>(&g_xh[8 * i])[0] = p0;
        reinterpret_cast<int4*>(&g_xh[8 * i])[1] = p1;
    }
    asm volatile("griddepcontrol.launch_dependents;" ::: "memory");
}

__device__ __forceinline__ void stg_cs_f4(float4* p, float4 v)
{
    asm volatile("st.global.cs.v4.f32 [%0], {%1,%2,%3,%4};"
                 :: "l"(p), "f"(v.x), "f"(v.y), "f"(v.z), "f"(v.w)
                 : "memory");
}

__global__ __launch_bounds__(256, 7)
void knn_mean_max_kernel(const int2* __restrict__ idx2,
                         float4*     __restrict__ out4,
                         int V)
{
    const int warp = (blockIdx.x * blockDim.x + threadIdx.x) >> 5;
    const int lane = threadIdx.x & 31;
    const int h    = lane >> 4;        // which vertex of the pair
    const int hl   = lane & 15;        // position within half-warp
    const int v    = 2 * warp + h;     // this half-warp's vertex
    const bool active = (v < V);

    // Coalesced idx load: lanes 0..31 cover 256B = idxs of both vertices.
    int2 pair = make_int2(0, 0);
    if (active) pair = idx2[v * (KNN / 2) + hl];

    // Block until convert's g_xh writes are visible.
    asm volatile("griddepcontrol.wait;" ::: "memory");

    if (!active) return;

    const __half2 zero = __float2half2_rn(0.0f);
    const __half2 ninf = __float2half2_rn(-65504.0f);
    __half2 sa0 = zero, sa1 = zero, sb0 = zero, sb1 = zero;  // 2x16 chains
    __half2 m0 = ninf, m1 = ninf;

    // Lane reads half2 pair (8B) at offset hl of each gathered row
    // (row = 32 half2 = 128B; 16 lanes * 8B cover it).
    const __half2* __restrict__ xl = g_xh + 2 * hl;
    const int srcbase = lane & 16;     // shuffles stay within the half-warp

    #pragma unroll
    for (int kk = 0; kk < KNN / 2; ++kk) {
        // k = 2*kk and k+1 live in the SAME source lane's int2.
        const int src  = srcbase + kk;
        const int idxE = __shfl_sync(0xffffffffu, pair.x, src);
        const int idxO = __shfl_sync(0xffffffffu, pair.y, src);
        const __half2* pE = xl + (size_t)(unsigned)idxE * (FDIM / 2);
        const __half2* pO = xl + (size_t)(unsigned)idxO * (FDIM / 2);

        // Both loads in ONE asm block (MLP=2; ptxas cannot re-serialize).
        unsigned int e0, e1, o0, o1;
        asm volatile(
            "ld.global.nc.v2.u32 {%0,%1}, [%4];\n\t"
            "ld.global.nc.v2.u32 {%2,%3}, [%5];\n\t"
            : "=r"(e0), "=r"(e1), "=r"(o0), "=r"(o1)
            : "l"(pE), "l"(pO));

        const __half2 ea = *(const __half2*)&e0;
        const __half2 eb = *(const __half2*)&e1;
        const __half2 oa = *(const __half2*)&o0;
        const __half2 ob = *(const __half2*)&o1;
        sa0 = __hadd2(sa0, ea);  sa1 = __hadd2(sa1, eb);
        sb0 = __hadd2(sb0, oa);  sb1 = __hadd2(sb1, ob);
        m0 = __hmax2(m0, ea);    m1 = __hmax2(m1, eb);
        m0 = __hmax2(m0, oa);    m1 = __hmax2(m1, ob);
    }

    const float2 f0a = __half22float2(sa0), f0b = __half22float2(sb0);
    const float2 f1a = __half22float2(sa1), f1b = __half22float2(sb1);
    const float2 fm0 = __half22float2(m0),  fm1 = __half22float2(m1);
    const float inv = 1.0f / KNN;

    // Lane holds features [4*hl, 4*hl+4) of vertex v.
    // out row = 128 floats = 32 float4: [mean 16 float4 | max 16 float4].
    float4 mean = make_float4((f0a.x + f0b.x) * inv, (f0a.y + f0b.y) * inv,
                              (f1a.x + f1b.x) * inv, (f1a.y + f1b.y) * inv);
    float4 mx   = make_float4(fm0.x, fm0.y, fm1.x, fm1.y);

    stg_cs_f4(&out4[v * 32 + hl],      mean);
    stg_cs_f4(&out4[v * 32 + 16 + hl], mx);
}

extern "C" void kernel_launch(void* const* d_in, const int* in_sizes, int n_in,
                              void* d_out, int out_size)
{
    const float4* x4   = (const float4*)d_in[0];  // x: [V, 64] float32
    const int2*   idx2 = (const int2*)d_in[1];    // idxs: [V, 32] int32
    float4*       out4 = (float4*)d_out;          // out: [V, 128] float32

    const int V   = in_sizes[0] / FDIM;           // 100000
    const int n16 = in_sizes[0] / 16;             // V*F/16 (32B per thread)

    convert_kernel<<<(n16 + 255) / 256, 256>>>(x4, n16);

    const int warps = (V + 1) / 2;                // 2 vertices per warp
    const int blocks = (warps + 7) / 8;           // 8 warps per block

    cudaLaunchConfig_t cfg = {};
    cfg.gridDim  = dim3((unsigned)blocks, 1, 1);
    cfg.blockDim = dim3(256, 1, 1);
    cfg.dynamicSmemBytes = 0;
    cfg.stream = 0;

    cudaLaunchAttribute attrs[1];
    attrs[0].id = cudaLaunchAttributeProgrammaticStreamSerialization;
    attrs[0].val.programmaticStreamSerializationAllowed = 1;
    cfg.attrs = attrs;
    cfg.numAttrs = 1;

    cudaLaunchKernelEx(&cfg, knn_mean_max_kernel, idx2, out4, V);
}